// round 13
// baseline (speedup 1.0000x reference)
#include <cuda_runtime.h>
#include <cuda_fp16.h>

// SpatialTransform: sample_grid = meshgrid + flow; warped = bilinear grid_sample
// (align_corners=True, border padding) of mov_image [16,4,512,512] f32.
// Output layout: [sample_grid (16*512*512*2 floats)] ++ [warped (16*4*512*512 floats)]
//
// R11 (= R9/R10 re-bench after two infra failures): fp16 pixel-pair scratch
// (2 scattered LDG.128 per output pixel).
//  - pack kernel: 4 px/thread, vectorized float4 reads, 64B writes.
//  - warp kernel: 2 px/thread (rows h, h+16) -> 4 gathers in flight (MLP 4).

#define B_ 16
#define C_ 4
#define H_ 512
#define W_ 512
#define PLANE (H_ * W_)
#define TILE 32

__device__ __forceinline__ unsigned int h2_to_u(half2 v) {
    return *reinterpret_cast<unsigned int*>(&v);
}
__device__ __forceinline__ half2 u_to_h2(unsigned int u) {
    return *reinterpret_cast<half2*>(&u);
}

// 67 MB scratch: [B, H, W] entries of 16B = {px w (4x half), px w+1 (4x half)}
__device__ uint4 d_scratch2[B_ * PLANE];

// ---------------- Pass 1: NCHW f32 -> paired NHWC fp16 ----------------
// Each thread handles 4 consecutive w. Per channel: one float4 + one scalar
// (clamped) load. Produces 4 consecutive 16B entries (64B).
__global__ __launch_bounds__(256) void pack_kernel(
    const float* __restrict__ img)     // [B,C,H,W]
{
    const int idx = blockIdx.x * blockDim.x + threadIdx.x;  // over B*H*(W/4)
    const int w4 = (idx & (W_ / 4 - 1)) << 2;
    const int h  = (idx >> 7) & (H_ - 1);
    const int b  = idx >> 16;

    const float* p = img + (size_t)b * (C_ * PLANE) + h * W_;
    const int wn = min(w4 + 4, W_ - 1);    // clamped next pixel (w4=508 -> 511)

    float v[C_][5];
#pragma unroll
    for (int c = 0; c < C_; c++) {
        const float4 q = __ldg(reinterpret_cast<const float4*>(p + c * PLANE + w4));
        v[c][0] = q.x; v[c][1] = q.y; v[c][2] = q.z; v[c][3] = q.w;
        v[c][4] = __ldg(p + c * PLANE + wn);
    }

    uint4* out = d_scratch2 + (size_t)b * PLANE + h * W_ + w4;
#pragma unroll
    for (int j = 0; j < 4; j++) {
        uint4 e;
        e.x = h2_to_u(__floats2half2_rn(v[0][j],     v[1][j]));
        e.y = h2_to_u(__floats2half2_rn(v[2][j],     v[3][j]));
        e.z = h2_to_u(__floats2half2_rn(v[0][j + 1], v[1][j + 1]));
        e.w = h2_to_u(__floats2half2_rn(v[2][j + 1], v[3][j + 1]));
        out[j] = e;
    }
}

// ---------------- Pass 2: warp with paired fp16 gathers, 2 px/thread ----------
__global__ __launch_bounds__(512) void warp_kernel(
    const float* __restrict__ flow,    // [B,H,W,2]
    float* __restrict__ grid_out,      // [B,H,W,2]
    float* __restrict__ warp_out)      // [B,C,H,W]
{
    const int lw = threadIdx.x & (TILE - 1);
    const int lh = threadIdx.x >> 5;               // 0..15
    const int w  = blockIdx.x * TILE + lw;
    const int b  = blockIdx.z;

    const uint4* sp = d_scratch2 + (size_t)b * PLANE;
    const float inv511 = 1.0f / 511.0f;
    const float gw = -1.0f + 2.0f * (float)w * inv511;

    const int h0 = blockIdx.y * TILE + lh;
    const int h1 = h0 + 16;
    const int pix0 = h0 * W_ + w;
    const int pix1 = h1 * W_ + w;

    // ---- pixel 0: coords + gathers issued ----
    const float2 fA = __ldg(reinterpret_cast<const float2*>(flow) + b * PLANE + pix0);
    const float dhA = (-1.0f + 2.0f * (float)h0 * inv511) + fA.x;
    const float dwA = gw + fA.y;
    reinterpret_cast<float2*>(grid_out)[b * PLANE + pix0] = make_float2(dwA, dhA);

    float xA = fminf(fmaxf((dwA + 1.0f) * 0.5f * 511.0f, 0.0f), 511.0f);
    float yA = fminf(fmaxf((dhA + 1.0f) * 0.5f * 511.0f, 0.0f), 511.0f);
    const float xA0f = floorf(xA), yA0f = floorf(yA);
    const float wxA = xA - xA0f, wyA = yA - yA0f;
    const int xA0 = (int)xA0f, yA0 = (int)yA0f;
    const int yA1 = min(yA0 + 1, H_ - 1);
    const uint4 eA0 = __ldg(sp + yA0 * W_ + xA0);
    const uint4 eA1 = __ldg(sp + yA1 * W_ + xA0);

    // ---- pixel 1: coords + gathers issued ----
    const float2 fB = __ldg(reinterpret_cast<const float2*>(flow) + b * PLANE + pix1);
    const float dhB = (-1.0f + 2.0f * (float)h1 * inv511) + fB.x;
    const float dwB = gw + fB.y;
    reinterpret_cast<float2*>(grid_out)[b * PLANE + pix1] = make_float2(dwB, dhB);

    float xB = fminf(fmaxf((dwB + 1.0f) * 0.5f * 511.0f, 0.0f), 511.0f);
    float yB = fminf(fmaxf((dhB + 1.0f) * 0.5f * 511.0f, 0.0f), 511.0f);
    const float xB0f = floorf(xB), yB0f = floorf(yB);
    const float wxB = xB - xB0f, wyB = yB - yB0f;
    const int xB0 = (int)xB0f, yB0 = (int)yB0f;
    const int yB1 = min(yB0 + 1, H_ - 1);
    const uint4 eB0 = __ldg(sp + yB0 * W_ + xB0);
    const uint4 eB1 = __ldg(sp + yB1 * W_ + xB0);

    float* wob = warp_out + (size_t)b * (C_ * PLANE);

    // ---- pixel 0: blend + write ----
    {
        const float w11 = wxA * wyA;
        const float w10 = wyA - w11;
        const float w01 = wxA - w11;
        const float w00 = 1.0f - wxA - wyA + w11;

        const float2 a01 = __half22float2(u_to_h2(eA0.x));
        const float2 a23 = __half22float2(u_to_h2(eA0.y));
        const float2 b01 = __half22float2(u_to_h2(eA0.z));
        const float2 b23 = __half22float2(u_to_h2(eA0.w));
        const float2 c01 = __half22float2(u_to_h2(eA1.x));
        const float2 c23 = __half22float2(u_to_h2(eA1.y));
        const float2 d01 = __half22float2(u_to_h2(eA1.z));
        const float2 d23 = __half22float2(u_to_h2(eA1.w));

        float* wo = wob + pix0;
        wo[0 * PLANE] = a01.x * w00 + b01.x * w01 + c01.x * w10 + d01.x * w11;
        wo[1 * PLANE] = a01.y * w00 + b01.y * w01 + c01.y * w10 + d01.y * w11;
        wo[2 * PLANE] = a23.x * w00 + b23.x * w01 + c23.x * w10 + d23.x * w11;
        wo[3 * PLANE] = a23.y * w00 + b23.y * w01 + c23.y * w10 + d23.y * w11;
    }

    // ---- pixel 1: blend + write ----
    {
        const float w11 = wxB * wyB;
        const float w10 = wyB - w11;
        const float w01 = wxB - w11;
        const float w00 = 1.0f - wxB - wyB + w11;

        const float2 a01 = __half22float2(u_to_h2(eB0.x));
        const float2 a23 = __half22float2(u_to_h2(eB0.y));
        const float2 b01 = __half22float2(u_to_h2(eB0.z));
        const float2 b23 = __half22float2(u_to_h2(eB0.w));
        const float2 c01 = __half22float2(u_to_h2(eB1.x));
        const float2 c23 = __half22float2(u_to_h2(eB1.y));
        const float2 d01 = __half22float2(u_to_h2(eB1.z));
        const float2 d23 = __half22float2(u_to_h2(eB1.w));

        float* wo = wob + pix1;
        wo[0 * PLANE] = a01.x * w00 + b01.x * w01 + c01.x * w10 + d01.x * w11;
        wo[1 * PLANE] = a01.y * w00 + b01.y * w01 + c01.y * w10 + d01.y * w11;
        wo[2 * PLANE] = a23.x * w00 + b23.x * w01 + c23.x * w10 + d23.x * w11;
        wo[3 * PLANE] = a23.y * w00 + b23.y * w01 + c23.y * w10 + d23.y * w11;
    }
}

extern "C" void kernel_launch(void* const* d_in, const int* in_sizes, int n_in,
                              void* d_out, int out_size)
{
    const float* img  = (const float*)d_in[0];   // mov_image [16,4,512,512]
    const float* flow = (const float*)d_in[1];   // flow      [16,512,512,2]
    float* grid_out = (float*)d_out;                                   // 16*512*512*2
    float* warp_out = (float*)d_out + (size_t)B_ * H_ * W_ * 2;        // 16*4*512*512

    const int nt = B_ * H_ * (W_ / 4);           // 1,048,576 threads
    pack_kernel<<<nt / 256, 256>>>(img);

    dim3 grid(W_ / TILE, H_ / TILE, B_);         // 16 x 16 x 16
    warp_kernel<<<grid, dim3(512)>>>(flow, grid_out, warp_out);
}